// round 14
// baseline (speedup 1.0000x reference)
#include <cuda_runtime.h>
#include <cstdint>

// EntropyCalculator: per-row histogram entropy.
//   x: [B, 64] int32 in [0,40)   out: [B,1] float32
// H = ln(64) - (ln2/64) * sum_v c_v log2(c_v)
//
// TMA-bulk staging: cp.async.bulk (UBLKCP) fills a 2-deep smem ring with raw
// 256-row tiles (16 x 4KB copies, 16B inter-group pad => conflict-free
// LDS.128 reads), mbarrier expect_tx completion. Warps never touch the global
// load path -> DRAM stream decoupled in hardware. Split-4 private byte
// histograms (16-deep RMW chains), MUFU entropy epilogue.

#define NT 256
#define GROUPS 16                 // 16 groups x 16 rows = 256 rows/tile
#define GROUP_B 4096              // bytes of row data per group
#define GPITCH 4112               // group pitch in smem (+16B pad)
#define SLOT_B (GROUPS * GPITCH)  // 65792 B per ring slot
#define TILE_B 65536              // gmem bytes per tile
#define NW 10                     // 40 bins as 4x8-bit byte counts per word

__device__ __forceinline__ void mbar_wait(uint32_t mbar, uint32_t phase) {
    asm volatile(
        "{\n\t.reg .pred P;\n"
        "WAIT_%=:\n\t"
        "mbarrier.try_wait.parity.acquire.cta.shared::cta.b64 P, [%0], %1;\n\t"
        "@!P bra WAIT_%=;\n\t}"
        :: "r"(mbar), "r"(phase) : "memory");
}

__global__ __launch_bounds__(NT) void entropy_hist_kernel(
    const char* __restrict__ x, float* __restrict__ out, int B, int ntiles)
{
    extern __shared__ char ring[];          // [slot0 | slot1], 2 x 65792 B
    __shared__ uint32_t h0[NW * NT];        // 4 DISTINCT objects -> 4
    __shared__ uint32_t h1[NW * NT];        // independent RMW chains
    __shared__ uint32_t h2[NW * NT];
    __shared__ uint32_t h3[NW * NT];
    __shared__ uint64_t mbar[2];

    const int tid = threadIdx.x;
    const uint32_t t4 = (uint32_t)tid << 2;
    unsigned char* p0 = (unsigned char*)h0;
    unsigned char* p1 = (unsigned char*)h1;
    unsigned char* p2 = (unsigned char*)h2;
    unsigned char* p3 = (unsigned char*)h3;

    #pragma unroll
    for (int i = 0; i < NW; i++) {
        h0[i * NT + tid] = 0u; h1[i * NT + tid] = 0u;
        h2[i * NT + tid] = 0u; h3[i * NT + tid] = 0u;
    }

    // Balanced contiguous tile range
    const int nb   = (int)gridDim.x;
    const int base = ntiles / nb, rem = ntiles % nb;
    const int my_n = base + ((int)blockIdx.x < rem);
    const int t0   = (int)blockIdx.x * base + min((int)blockIdx.x, rem);
    if (my_n == 0) return;

    const uint32_t rb  = (uint32_t)__cvta_generic_to_shared(ring);
    const uint32_t mb0 = (uint32_t)__cvta_generic_to_shared(&mbar[0]);

    if (tid == 0) {
        asm volatile("mbarrier.init.shared.b64 [%0], 1;" :: "r"(mb0)     : "memory");
        asm volatile("mbarrier.init.shared.b64 [%0], 1;" :: "r"(mb0 + 8) : "memory");
    }
    __syncthreads();

    // Issue tile -> ring slot: 16 bulk copies of 4 KB, one expect_tx of 64 KB.
    #define ISSUE(TILE, S)                                                     \
    do {                                                                       \
        uint32_t mb_ = mb0 + (uint32_t)((S) * 8);                              \
        asm volatile("mbarrier.arrive.expect_tx.shared.b64 _, [%0], %1;"       \
                     :: "r"(mb_), "r"(TILE_B) : "memory");                     \
        const char* src_ = x + (size_t)(TILE) * TILE_B;                        \
        uint32_t db_ = rb + (uint32_t)((S) * SLOT_B);                          \
        _Pragma("unroll")                                                      \
        for (int g_ = 0; g_ < GROUPS; g_++) {                                  \
            asm volatile(                                                      \
              "cp.async.bulk.shared::cluster.global.mbarrier::complete_tx::bytes " \
              "[%0], [%1], %2, [%3];"                                          \
              :: "r"(db_ + g_ * GPITCH), "l"(src_ + g_ * GROUP_B),             \
                 "r"(GROUP_B), "r"(mb_) : "memory");                           \
        }                                                                      \
    } while (0)

    if (tid == 0) {
        ISSUE(t0, 0);
        if (my_n > 1) ISSUE(t0 + 1, 1);
    }

    // This thread's row: group g (pitch 4112B), row-in-group ri.
    const int g  = tid & 15;
    const int ri = tid >> 4;
    uint32_t ph0 = 0, ph1 = 0;

    for (int i = 0; i < my_n; i++) {
        const int s = i & 1;
        if (s == 0) { mbar_wait(mb0,     ph0); ph0 ^= 1; }
        else        { mbar_wait(mb0 + 8, ph1); ph1 ^= 1; }

        // ---- histogram own row: 16 LDS.128, optimal 4-phase (pad-pitch);
        // raw values -> no extraction; 64 byte-RMWs over 4 distinct arrays.
        // NT=256 byte addr bits: [0:1]=v&3, [2:9]=tid, [10:13]=v>>2.
        const uint4* myrow = (const uint4*)(ring + s * SLOT_B + g * GPITCH + ri * 256);
        #pragma unroll
        for (int j = 0; j < 16; j++) {
            uint4 q = myrow[j];
            p0[(((q.x & 0x3Cu) << 8) | (q.x & 3u)) + t4]++;
            p1[(((q.y & 0x3Cu) << 8) | (q.y & 3u)) + t4]++;
            p2[(((q.z & 0x3Cu) << 8) | (q.z & 3u)) + t4]++;
            p3[(((q.w & 0x3Cu) << 8) | (q.w & 3u)) + t4]++;
        }

        // ---- merge (byte sums <= 64: no carry crossing), re-zero, entropy.
        float acc = 0.0f;
        #pragma unroll
        for (int wi = 0; wi < NW; wi++) {
            uint32_t w = h0[wi * NT + tid] + h1[wi * NT + tid]
                       + h2[wi * NT + tid] + h3[wi * NT + tid];
            h0[wi * NT + tid] = 0u; h1[wi * NT + tid] = 0u;
            h2[wi * NT + tid] = 0u; h3[wi * NT + tid] = 0u;
            #pragma unroll
            for (int b = 0; b < 4; b++) {
                float cf = (float)((w >> (8 * b)) & 0xFFu);
                acc += cf * __log2f(fmaxf(cf, 1.0f));   // c = 0,1 -> 0
            }
        }
        int row = (t0 + i) * NT + g * 16 + ri;
        if (row < B)
            out[row] = 4.1588830833596718565f - acc * 0.010830424696159069f;

        __syncthreads();                    // all threads done reading slot s
        if (tid == 0 && i + 2 < my_n) ISSUE(t0 + i + 2, s);
    }
    #undef ISSUE
}

extern "C" void kernel_launch(void* const* d_in, const int* in_sizes, int n_in,
                              void* d_out, int out_size)
{
    const char* x = (const char*)d_in[0];
    float* out    = (float*)d_out;
    int B = in_sizes[0] / 64;             // 262144 rows
    int ntiles = B / NT;                  // 1024 exact for this dataset

    const int SMEM = 2 * SLOT_B;          // 131584 B dynamic
    cudaFuncSetAttribute(entropy_hist_kernel,
                         cudaFuncAttributeMaxDynamicSharedMemorySize, SMEM);

    int grid = 148;                       // 1 block/SM, persistent
    if (grid > ntiles) grid = ntiles;
    entropy_hist_kernel<<<grid, NT, SMEM>>>(x, out, B, ntiles);
}

// round 15
// speedup vs baseline: 1.1067x; 1.1067x over previous
#include <cuda_runtime.h>
#include <cstdint>

// EntropyCalculator: per-row histogram entropy.
//   x: [B, 64] int32 in [0,40)   out: [B,1] float32
// H = ln(64) - (ln2/64) * sum_v c_v log2(c_v)
//
// Producer/consumer decoupling: TMA bulk (cp.async.bulk) producer fills a
// 3-deep ring of raw 256-row tiles, re-armed by tid0 as soon as all 512
// consumers arrive-empty -> producer runs 2-3 tiles ahead; consumers (16
// warps) never issue global loads. 2 threads per row (32-element RMW chains),
// intra-warp partner merge, MUFU entropy.

#define NT 512
#define TROWS 256                  // rows per tile
#define GROUPS 16
#define GROUP_B 4096
#define GPITCH 4112                // +16B pad per group
#define SLOT_B (GROUPS * GPITCH)   // 65792
#define TILE_B 65536
#define DEPTH 3
#define NW 10                      // 40 bins as 4x8-bit byte counts per word

#define RING_B (DEPTH * SLOT_B)          // 197376
#define HIST_OFF RING_B
#define HIST_B (NW * NT * 4)             // 20480
#define MBAR_OFF (HIST_OFF + HIST_B)     // full[3] then empty[3]
#define SMEM_TOTAL (MBAR_OFF + 64)       // 217920 B

__device__ __forceinline__ void mbar_wait(uint32_t mbar, uint32_t phase) {
    asm volatile(
        "{\n\t.reg .pred P;\n"
        "WAIT_%=:\n\t"
        "mbarrier.try_wait.parity.acquire.cta.shared::cta.b64 P, [%0], %1;\n\t"
        "@!P bra WAIT_%=;\n\t}"
        :: "r"(mbar), "r"(phase) : "memory");
}

__global__ __launch_bounds__(NT, 1) void entropy_hist_kernel(
    const char* __restrict__ x, float* __restrict__ out, int ntiles)
{
    extern __shared__ char smem[];
    uint32_t*      hist = (uint32_t*)(smem + HIST_OFF);
    unsigned char* h8   = (unsigned char*)hist;

    const int tid = threadIdx.x;
    const uint32_t sb = (uint32_t)__cvta_generic_to_shared(smem);
    const uint32_t mb = sb + MBAR_OFF;          // full[s]=mb+8s, empty[s]=mb+24+8s
    const uint32_t t4 = (uint32_t)tid << 2;

    if (tid == 0) {
        #pragma unroll
        for (int s = 0; s < DEPTH; s++) {
            asm volatile("mbarrier.init.shared.b64 [%0], 1;"
                         :: "r"(mb + s * 8) : "memory");
            asm volatile("mbarrier.init.shared.b64 [%0], %1;"
                         :: "r"(mb + 24 + s * 8), "r"(NT) : "memory");
        }
    }
    #pragma unroll
    for (int i = 0; i < NW; i++) hist[i * NT + tid] = 0u;
    __syncthreads();

    // Balanced contiguous tile range
    const int nb   = (int)gridDim.x;
    const int base = ntiles / nb, rem = ntiles % nb;
    const int my_n = base + ((int)blockIdx.x < rem);
    const int t0   = (int)blockIdx.x * base + min((int)blockIdx.x, rem);
    if (my_n == 0) return;

    // Issue tile -> slot: re-arm full[s] (expect 64KB), 16 x 4KB bulk copies.
    #define ISSUE(TILE, S)                                                     \
    do {                                                                       \
        uint32_t mb_ = mb + (uint32_t)((S) * 8);                               \
        asm volatile("mbarrier.arrive.expect_tx.shared.b64 _, [%0], %1;"       \
                     :: "r"(mb_), "r"(TILE_B) : "memory");                     \
        const char* src_ = x + (size_t)(TILE) * TILE_B;                        \
        uint32_t db_ = sb + (uint32_t)((S) * SLOT_B);                          \
        _Pragma("unroll")                                                      \
        for (int g_ = 0; g_ < GROUPS; g_++) {                                  \
            asm volatile(                                                      \
              "cp.async.bulk.shared::cluster.global.mbarrier::complete_tx::bytes " \
              "[%0], [%1], %2, [%3];"                                          \
              :: "r"(db_ + g_ * GPITCH), "l"(src_ + g_ * GROUP_B),             \
                 "r"(GROUP_B), "r"(mb_) : "memory");                           \
        }                                                                      \
    } while (0)

    if (tid == 0) {
        const int pre = my_n < DEPTH ? my_n : DEPTH;
        for (int p = 0; p < pre; p++) ISSUE(t0 + p, p);
    }

    // This thread: row rr (half h). Half-row = 128 B = 8 granules of 16 B.
    const int rr = tid >> 1, h = tid & 1;
    const uint32_t half_off = (uint32_t)((rr >> 4) * GPITCH + (rr & 15) * 256 + h * 128);
    const uint32_t lane7x16 = (uint32_t)(tid & 7) << 4;   // XOR swizzle (x16 B)

    for (int i = 0; i < my_n; i++) {
        const int r = i / DEPTH;
        const int s = i - r * DEPTH;
        const uint32_t ph = (uint32_t)(r & 1);

        mbar_wait(mb + s * 8, ph);                 // tile (t0+i) ready in slot s

        // ---- 8 LDS.128 (xor-swizzled: optimal 4-phase) + 32 byte-RMWs ------
        // NT=512 byte addr bits: [0:1]=v&3, [2:10]=tid, [11:14]=v>>2.
        const char* hp = smem + s * SLOT_B + half_off;
        #pragma unroll
        for (int j = 0; j < 8; j++) {
            uint4 q = *(const uint4*)(hp + (((uint32_t)(j << 4)) ^ lane7x16));
            h8[(((q.x & 0x3Cu) << 9) | (q.x & 3u)) + t4]++;
            h8[(((q.y & 0x3Cu) << 9) | (q.y & 3u)) + t4]++;
            h8[(((q.z & 0x3Cu) << 9) | (q.z & 3u)) + t4]++;
            h8[(((q.w & 0x3Cu) << 9) | (q.w & 3u)) + t4]++;
        }
        // Done reading slot s
        asm volatile("mbarrier.arrive.shared.b64 _, [%0];"
                     :: "r"(mb + 24 + s * 8) : "memory");

        __syncwarp();                              // partner (tid^1) RMWs visible

        // ---- merge partner columns + entropy (h==0 lanes only) -------------
        float acc = 0.0f;
        if (h == 0) {
            #pragma unroll
            for (int wi = 0; wi < NW; wi++) {
                uint32_t w = hist[wi * NT + tid] + hist[wi * NT + tid + 1];
                #pragma unroll
                for (int b = 0; b < 4; b++) {
                    float cf = (float)((w >> (8 * b)) & 0xFFu);
                    acc += cf * __log2f(fmaxf(cf, 1.0f));   // c = 0,1 -> 0
                }
            }
        }
        __syncwarp();                              // merge reads done before zeroing
        #pragma unroll
        for (int wi = 0; wi < NW; wi++) hist[wi * NT + tid] = 0u;
        if (h == 0)
            out[(size_t)(t0 + i) * TROWS + rr] =
                4.1588830833596718565f - acc * 0.010830424696159069f;

        // ---- producer: re-arm slot s with tile i+DEPTH once all 512 emptied
        if (tid == 0 && i + DEPTH < my_n) {
            mbar_wait(mb + 24 + s * 8, ph);        // 512 empty-arrivals this round
            ISSUE(t0 + i + DEPTH, s);
        }
    }
    #undef ISSUE
}

extern "C" void kernel_launch(void* const* d_in, const int* in_sizes, int n_in,
                              void* d_out, int out_size)
{
    const char* x = (const char*)d_in[0];
    float* out    = (float*)d_out;
    int B = in_sizes[0] / 64;              // 262144 rows
    int ntiles = B / TROWS;                // 1024 exact

    cudaFuncSetAttribute(entropy_hist_kernel,
                         cudaFuncAttributeMaxDynamicSharedMemorySize, SMEM_TOTAL);

    int grid = 148;                        // 1 block/SM, persistent
    if (grid > ntiles) grid = ntiles;
    entropy_hist_kernel<<<grid, NT, SMEM_TOTAL>>>(x, out, ntiles);
}

// round 16
// speedup vs baseline: 1.3545x; 1.2239x over previous
#include <cuda_runtime.h>
#include <cstdint>

// EntropyCalculator: per-row histogram entropy.
//   x: [B, 64] int32 in [0,40)   out: [B,1] float32
// H = ln(64) - (1/64) * sum_v c_v ln c_v
//
// Warp-autonomous, instruction-minimal:
//  - each warp stages its own 32 rows RAW via cp.async (no reg round-trip,
//    no packing, per-warp wait_group + __syncwarp -> zero block barriers
//    after startup)
//  - XOR-granule swizzle: conflict-free cp.async writes + 4-phase LDS.128
//  - split-2 distinct hists (RMW chain depth 32), LUT epilogue

#define NT 128     // 4 warps x 32 rows
#define NW 10      // 40 bins as 4x8-bit byte counts per word

__global__ __launch_bounds__(NT, 5) void entropy_hist_kernel(
    const int4* __restrict__ x, float* __restrict__ out, int B)
{
    __shared__ uint32_t tile[NT * 64];   // raw ids, 256 B/row, XOR-swizzled (32 KB)
    __shared__ uint32_t h0[NW * NT];     // two DISTINCT objects ->
    __shared__ uint32_t h1[NW * NT];     // two independent RMW chains
    __shared__ float    lut[72];         // lut[c] = c*ln(c)/64

    const int tid  = threadIdx.x;
    const int lane = tid & 31;
    const int wrp  = tid >> 5;
    const uint32_t t4 = (uint32_t)tid << 2;
    unsigned char* b0 = (unsigned char*)h0;
    unsigned char* b1 = (unsigned char*)h1;

    if (tid < 72) lut[tid] = (tid == 0) ? 0.0f
                           : (float)tid * logf((float)tid) * 0.015625f;
    #pragma unroll
    for (int i = 0; i < NW; i++) { h0[i * NT + tid] = 0u; h1[i * NT + tid] = 0u; }
    __syncthreads();                       // lut visible; only barrier in kernel

    // ---- warp-local staging: 32 rows = 8 KB, cp.async 16 x 16B per lane ----
    const int row0 = blockIdx.x * NT + wrp * 32;
    if (row0 >= B) return;
    const int  rows  = min(32, B - row0);
    const int  e_lim = rows * 16;
    const int4* gp = x + (size_t)row0 * 16;                 // warp's 512 int4
    const uint32_t tb = (uint32_t)__cvta_generic_to_shared(tile)
                      + (uint32_t)(wrp * 8192);
    #pragma unroll
    for (int k = 0; k < 16; k++) {
        int e = k * 32 + lane;                              // coalesced 512 B/instr
        if (e < e_lim) {
            int r = e >> 4, j = e & 15;                     // local row, granule
            uint32_t dst = tb + (uint32_t)((r << 8) + (((uint32_t)j ^ (r & 7)) << 4));
            asm volatile("cp.async.cg.shared.global [%0], [%1], 16;"
                         :: "r"(dst), "l"(gp + e));
        }
    }
    asm volatile("cp.async.commit_group;" ::: "memory");
    asm volatile("cp.async.wait_group 0;" ::: "memory");
    __syncwarp();                          // all lanes' copies visible warp-wide

    if (lane >= rows) return;

    // ---- histogram own row: 16 LDS.128 (4-phase via swizzle), raw values ->
    // zero extraction; 64 byte-RMWs alternating two distinct arrays.
    // NT=128 byte addr bits: [0:1]=v&3, [2:8]=tid, [9:12]=v>>2 (disjoint).
    const char* hp = (const char*)tile + wrp * 8192 + lane * 256;
    const uint32_t sw = (uint32_t)(lane & 7) << 4;
    #pragma unroll
    for (int j = 0; j < 16; j++) {
        uint4 q = *(const uint4*)(hp + (((uint32_t)j << 4) ^ sw));
        b0[(((q.x & 0x3Cu) << 7) | (q.x & 3u)) + t4]++;
        b1[(((q.y & 0x3Cu) << 7) | (q.y & 3u)) + t4]++;
        b0[(((q.z & 0x3Cu) << 7) | (q.z & 3u)) + t4]++;
        b1[(((q.w & 0x3Cu) << 7) | (q.w & 3u)) + t4]++;
    }

    // ---- entropy via LUT: merge split hists (byte sums <= 64, no carry
    // crossing) and accumulate c*ln(c)/64 --------------------------------
    float acc = 0.0f;
    #pragma unroll
    for (int i = 0; i < NW; i++) {
        uint32_t w = h0[i * NT + tid] + h1[i * NT + tid];
        acc += lut[w & 0xFFu];
        acc += lut[(w >> 8) & 0xFFu];
        acc += lut[(w >> 16) & 0xFFu];
        acc += lut[w >> 24];
    }
    out[row0 + lane] = 4.1588830833596718565f - acc;       // ln(64) - acc
}

extern "C" void kernel_launch(void* const* d_in, const int* in_sizes, int n_in,
                              void* d_out, int out_size)
{
    const int4* x = (const int4*)d_in[0];
    float* out    = (float*)d_out;
    int B = in_sizes[0] / 64;
    int grid = (B + NT - 1) / NT;
    entropy_hist_kernel<<<grid, NT>>>(x, out, B);
}

// round 17
// speedup vs baseline: 1.3750x; 1.0152x over previous
#include <cuda_runtime.h>
#include <cstdint>

// EntropyCalculator: per-row histogram entropy.
//   x: [B, 64] int32 in [0,40)   out: [B,1] float32
// H = ln(64) - (1/64) * sum_v c_v ln c_v
//
// Max-occupancy cell: NT=256, 6 blocks/SM (48 warps) via a ZERO-PAD packed
// tile (16 KB, XOR-granule swizzle: granule g of row r at g^(r&3) -> both the
// packing STS and the LDS.128 reads are conflict-free), split-2 distinct
// histograms (RMW chain depth 32), conflict-free LUT epilogue, one startup
// barrier then fully warp-autonomous.

#define NT 256
#define NW 10      // 40 bins as 4x8-bit byte counts per word

__global__ __launch_bounds__(NT) void entropy_hist_kernel(
    const int4* __restrict__ x, float* __restrict__ out, int B)
{
    __shared__ uint32_t tile[NT * 16];   // packed ids, 64B/row, swizzled (16 KB)
    __shared__ uint32_t h0[NW * NT];     // two DISTINCT objects ->
    __shared__ uint32_t h1[NW * NT];     // two independent RMW chains
    __shared__ float    lut[72];         // lut[c] = c*ln(c)/64

    const int tid  = threadIdx.x;
    const int lane = tid & 31;
    const int wrp  = tid >> 5;
    const uint32_t t4 = (uint32_t)tid << 2;
    unsigned char* b0 = (unsigned char*)h0;
    unsigned char* b1 = (unsigned char*)h1;

    if (tid < 72) lut[tid] = (tid == 0) ? 0.0f
                           : (float)tid * logf((float)tid) * 0.015625f;
    #pragma unroll
    for (int i = 0; i < NW; i++) { h0[i * NT + tid] = 0u; h1[i * NT + tid] = 0u; }
    __syncthreads();                     // lut visible; only block barrier

    // ---- warp-local staging: 32 rows, coalesced LDG.128 + PRMT pack + STS.
    // Packed word (r, j): granule j>>2 swizzled by r&3 -> conflict-free STS
    // (fixed k: 2 rows x 16 words span all 32 banks) and LDS.128 (4-phase).
    const int row0 = blockIdx.x * NT + wrp * 32;
    if (row0 >= B) return;
    const int rows = min(32, B - row0);
    const int e_lim = rows * 16;
    const int4* gp = x + (size_t)row0 * 16;
    uint32_t* tw = tile + wrp * (32 * 16);         // warp-private 512 words
    #pragma unroll
    for (int k = 0; k < 16; k++) {
        int e = k * 32 + lane;                     // coalesced 512 B per instr
        if (e < e_lim) {
            int4 w = __ldg(&gp[e]);
            uint32_t a = __byte_perm((uint32_t)w.x, (uint32_t)w.y, 0x0040);
            uint32_t b = __byte_perm((uint32_t)w.z, (uint32_t)w.w, 0x0040);
            uint32_t p = __byte_perm(a, b, 0x5410);
            int r = e >> 4, j = e & 15;
            tw[(r << 4) + ((((j >> 2) ^ (r & 3)) << 2) | (j & 3))] = p;
        }
    }
    __syncwarp();

    if (lane < rows) {
        // ---- histogram own row: 4 LDS.128 (4-phase via swizzle), 64 byte
        // RMWs alternating two distinct arrays (two depth-32 chains).
        // NT=256 byte addr bits: [0:1]=v&3, [2:9]=tid, [10:13]=v>>2.
        const uint32_t* my = tw + (lane << 4);
        const uint32_t rm = (uint32_t)(lane & 3);
        #pragma unroll
        for (int g = 0; g < 4; g++) {
            uint4 q = *(const uint4*)(my + (((uint32_t)g ^ rm) << 2));
            uint32_t ws[4] = {q.x, q.y, q.z, q.w};
            #pragma unroll
            for (int u = 0; u < 4; u++) {
                uint32_t p = ws[u];
                uint32_t v0 = __byte_perm(p, 0u, 0x4440);
                uint32_t v1 = __byte_perm(p, 0u, 0x4441);
                uint32_t v2 = __byte_perm(p, 0u, 0x4442);
                uint32_t v3 = __byte_perm(p, 0u, 0x4443);
                b0[(((v0 & 0x3Cu) << 8) | (v0 & 3u)) + t4]++;
                b1[(((v1 & 0x3Cu) << 8) | (v1 & 3u)) + t4]++;
                b0[(((v2 & 0x3Cu) << 8) | (v2 & 3u)) + t4]++;
                b1[(((v3 & 0x3Cu) << 8) | (v3 & 3u)) + t4]++;
            }
        }

        // ---- entropy: merge split hists (byte sums <= 64, no carry
        // crossing), LUT lookups are broadcast/conflict-free ---------------
        float acc = 0.0f;
        #pragma unroll
        for (int i = 0; i < NW; i++) {
            uint32_t w = h0[i * NT + tid] + h1[i * NT + tid];
            acc += lut[w & 0xFFu];
            acc += lut[(w >> 8) & 0xFFu];
            acc += lut[(w >> 16) & 0xFFu];
            acc += lut[w >> 24];
        }
        out[row0 + lane] = 4.1588830833596718565f - acc;    // ln(64) - acc
    }
}

extern "C" void kernel_launch(void* const* d_in, const int* in_sizes, int n_in,
                              void* d_out, int out_size)
{
    const int4* x = (const int4*)d_in[0];
    float* out    = (float*)d_out;
    int B = in_sizes[0] / 64;
    int grid = (B + NT - 1) / NT;
    entropy_hist_kernel<<<grid, NT>>>(x, out, B);
}